// round 1
// baseline (speedup 1.0000x reference)
#include <cuda_runtime.h>

#define NNODE 17
#define GPB   16                 // graphs per block
#define TPB   (NNODE * GPB)      // 272 threads

typedef unsigned long long u64;

// packed fp32x2 FMA (Blackwell); ptxas never auto-fuses this from C++
__device__ __forceinline__ u64 ffma2(u64 a, u64 b, u64 c) {
    u64 d;
    asm("fma.rn.f32x2 %0, %1, %2, %3;" : "=l"(d) : "l"(a), "l"(b), "l"(c));
    return d;
}
__device__ __forceinline__ u64 bcast2(float v) {
    u64 d; unsigned r = __float_as_uint(v);
    asm("mov.b64 %0, {%1, %1};" : "=l"(d) : "r"(r));
    return d;
}
__device__ __forceinline__ void unpk(u64 d, float& x, float& y) {
    unsigned a, b;
    asm("mov.b64 {%0, %1}, %2;" : "=r"(a), "=r"(b) : "l"(d));
    x = __uint_as_float(a); y = __uint_as_float(b);
}

__global__ void __launch_bounds__(TPB, 2)
gnn_fused(const float* __restrict__ z,
          const float* __restrict__ fc_w, const float* __restrict__ fc_b,
          const float* __restrict__ w1,   const float* __restrict__ b1,
          const float* __restrict__ w2,   const float* __restrict__ b2,
          const float* __restrict__ w3,   const float* __restrict__ b3,
          float* __restrict__ out)
{
    // weights: w1[8x16] | b1[16] | w2[16x32] | b2[32] | w3[32x32] | b3[32]
    __shared__ __align__(16) float wsh[1744];
    // arena reused per stage: z+x0 -> x1 -> x2 -> out staging
    __shared__ __align__(16) unsigned char arena[39168];

    float* w1s = wsh;
    float* b1s = wsh + 128;
    float* w2s = wsh + 144;
    float* b2s = wsh + 656;
    float* w3s = wsh + 688;
    float* b3s = wsh + 1712;

    const int tid = threadIdx.x;
    for (int i = tid; i < 128;  i += TPB) w1s[i] = w1[i];
    if (tid < 16)                         b1s[tid] = b1[tid];
    for (int i = tid; i < 512;  i += TPB) w2s[i] = w2[i];
    if (tid < 32)                         b2s[tid] = b2[tid];
    for (int i = tid; i < 1024; i += TPB) w3s[i] = w3[i];
    if (tid < 32)                         b3s[tid] = b3[tid];

    float* zs  = (float*)arena;              // [GPB][32]
    float* x0b = (float*)(arena + 2048);     // [272][12] (8 used, pad 12)
    const float* zblk = z + (size_t)blockIdx.x * (GPB * 32);
    for (int i = tid; i < GPB * 32; i += TPB) zs[i] = zblk[i];
    __syncthreads();

    const int g  = tid / NNODE;
    const int n  = tid - g * NNODE;
    const int rp = (n == NNODE - 1) ? tid - (NNODE - 1) : tid + 1;  // row of (n+1)%17
    const int rm = (n == 0)         ? tid + (NNODE - 1) : tid - 1;  // row of (n-1)%17
    const float s3 = (1.0f / 3.0f);

    // ================= FC: x0[n] = z @ fc_w[:, 8n:8n+8] + fc_b =================
    u64 acc0[4];
    {
        const u64* fb = (const u64*)fc_b + n * 4;
        #pragma unroll
        for (int i = 0; i < 4; i++) acc0[i] = __ldg(fb + i);
        const float* zg = zs + g * 32;
        #pragma unroll
        for (int k = 0; k < 32; k++) {
            u64 zz = bcast2(zg[k]);
            const ulonglong2* w = (const ulonglong2*)(fc_w + k * 136 + n * 8);
            ulonglong2 wa = __ldg(w);
            ulonglong2 wb = __ldg(w + 1);
            acc0[0] = ffma2(zz, wa.x, acc0[0]);
            acc0[1] = ffma2(zz, wa.y, acc0[1]);
            acc0[2] = ffma2(zz, wb.x, acc0[2]);
            acc0[3] = ffma2(zz, wb.y, acc0[3]);
        }
    }
    float x0f[8];
    #pragma unroll
    for (int i = 0; i < 4; i++) unpk(acc0[i], x0f[2 * i], x0f[2 * i + 1]);
    {
        float4* row = (float4*)(x0b + tid * 12);
        row[0] = make_float4(x0f[0], x0f[1], x0f[2], x0f[3]);
        row[1] = make_float4(x0f[4], x0f[5], x0f[6], x0f[7]);
    }
    __syncthreads();

    float a0[8];
    {
        const float4* p = (const float4*)(x0b + rp * 12);
        const float4* m = (const float4*)(x0b + rm * 12);
        float4 p0 = p[0], p1 = p[1], m0 = m[0], m1 = m[1];
        a0[0] = (x0f[0] + p0.x + m0.x) * s3;  a0[1] = (x0f[1] + p0.y + m0.y) * s3;
        a0[2] = (x0f[2] + p0.z + m0.z) * s3;  a0[3] = (x0f[3] + p0.w + m0.w) * s3;
        a0[4] = (x0f[4] + p1.x + m1.x) * s3;  a0[5] = (x0f[5] + p1.y + m1.y) * s3;
        a0[6] = (x0f[6] + p1.z + m1.z) * s3;  a0[7] = (x0f[7] + p1.w + m1.w) * s3;
    }
    __syncthreads();

    // ================= conv1: x1 = relu(a0 @ w1 + b1) (16 out) =================
    float* x1b = (float*)arena;              // [272][20] (16 used, pad 20)
    u64 acc1[8];
    #pragma unroll
    for (int j = 0; j < 8; j++) acc1[j] = *((const u64*)b1s + j);
    #pragma unroll
    for (int k = 0; k < 8; k++) {
        u64 av = bcast2(a0[k]);
        const u64* wr = (const u64*)(w1s + k * 16);
        #pragma unroll
        for (int j = 0; j < 8; j++) acc1[j] = ffma2(av, wr[j], acc1[j]);
    }
    float x1f[16];
    #pragma unroll
    for (int j = 0; j < 8; j++) unpk(acc1[j], x1f[2 * j], x1f[2 * j + 1]);
    #pragma unroll
    for (int j = 0; j < 16; j++) x1f[j] = fmaxf(x1f[j], 0.0f);
    {
        float4* row = (float4*)(x1b + tid * 20);
        #pragma unroll
        for (int q = 0; q < 4; q++)
            row[q] = make_float4(x1f[4*q], x1f[4*q+1], x1f[4*q+2], x1f[4*q+3]);
    }
    __syncthreads();

    float a1[16];
    {
        const float4* p = (const float4*)(x1b + rp * 20);
        const float4* m = (const float4*)(x1b + rm * 20);
        #pragma unroll
        for (int q = 0; q < 4; q++) {
            float4 pv = p[q], mv = m[q];
            a1[4*q+0] = (x1f[4*q+0] + pv.x + mv.x) * s3;
            a1[4*q+1] = (x1f[4*q+1] + pv.y + mv.y) * s3;
            a1[4*q+2] = (x1f[4*q+2] + pv.z + mv.z) * s3;
            a1[4*q+3] = (x1f[4*q+3] + pv.w + mv.w) * s3;
        }
    }
    __syncthreads();

    // ================= conv2: x2 = relu(a1 @ w2 + b2) (32 out) =================
    float* x2b = (float*)arena;              // [272][36] (32 used, pad 36)
    u64 acc2[16];
    #pragma unroll
    for (int j = 0; j < 16; j++) acc2[j] = *((const u64*)b2s + j);
    #pragma unroll
    for (int k = 0; k < 16; k++) {
        u64 av = bcast2(a1[k]);
        const u64* wr = (const u64*)(w2s + k * 32);
        #pragma unroll
        for (int j = 0; j < 16; j++) acc2[j] = ffma2(av, wr[j], acc2[j]);
    }
    float x2f[32];
    #pragma unroll
    for (int j = 0; j < 16; j++) unpk(acc2[j], x2f[2 * j], x2f[2 * j + 1]);
    #pragma unroll
    for (int j = 0; j < 32; j++) x2f[j] = fmaxf(x2f[j], 0.0f);
    {
        float4* row = (float4*)(x2b + tid * 36);
        #pragma unroll
        for (int q = 0; q < 8; q++)
            row[q] = make_float4(x2f[4*q], x2f[4*q+1], x2f[4*q+2], x2f[4*q+3]);
    }
    __syncthreads();

    float a2[32];
    {
        const float4* p = (const float4*)(x2b + rp * 36);
        const float4* m = (const float4*)(x2b + rm * 36);
        #pragma unroll
        for (int q = 0; q < 8; q++) {
            float4 pv = p[q], mv = m[q];
            a2[4*q+0] = (x2f[4*q+0] + pv.x + mv.x) * s3;
            a2[4*q+1] = (x2f[4*q+1] + pv.y + mv.y) * s3;
            a2[4*q+2] = (x2f[4*q+2] + pv.z + mv.z) * s3;
            a2[4*q+3] = (x2f[4*q+3] + pv.w + mv.w) * s3;
        }
    }
    __syncthreads();

    // ================= conv3: out = a2 @ w3 + b3 (32 out, no relu) =============
    u64 acc3[16];
    #pragma unroll
    for (int j = 0; j < 16; j++) acc3[j] = *((const u64*)b3s + j);
    #pragma unroll
    for (int k = 0; k < 32; k++) {
        u64 av = bcast2(a2[k]);
        const u64* wr = (const u64*)(w3s + k * 32);
        #pragma unroll
        for (int j = 0; j < 16; j++) acc3[j] = ffma2(av, wr[j], acc3[j]);
    }
    float of[32];
    #pragma unroll
    for (int j = 0; j < 16; j++) unpk(acc3[j], of[2 * j], of[2 * j + 1]);
    {
        float4* row = (float4*)(x2b + tid * 36);   // reuse big buffer as staging
        #pragma unroll
        for (int q = 0; q < 8; q++)
            row[q] = make_float4(of[4*q], of[4*q+1], of[4*q+2], of[4*q+3]);
    }
    __syncthreads();

    // coalesced global write: 16*17*32 floats contiguous per block
    float4* og = (float4*)(out + (size_t)blockIdx.x * (GPB * NNODE * 32));
    const float* src = (const float*)arena;
    for (int q = tid; q < GPB * NNODE * 8; q += TPB) {
        int row = q >> 3, c = q & 7;
        og[q] = *(const float4*)(src + row * 36 + c * 4);
    }
}

extern "C" void kernel_launch(void* const* d_in, const int* in_sizes, int n_in,
                              void* d_out, int out_size) {
    const float* z    = (const float*)d_in[0];
    // d_in[1] = edge_index: fixed ring topology, degree==3 everywhere -> norm==1/3; unused
    const float* fc_w = (const float*)d_in[2];
    const float* fc_b = (const float*)d_in[3];
    const float* w1   = (const float*)d_in[4];
    const float* b1   = (const float*)d_in[5];
    const float* w2   = (const float*)d_in[6];
    const float* b2   = (const float*)d_in[7];
    const float* w3   = (const float*)d_in[8];
    const float* b3   = (const float*)d_in[9];

    const int B    = in_sizes[0] / 32;      // 65536 graphs
    const int grid = B / GPB;               // 4096 blocks
    gnn_fused<<<grid, TPB>>>(z, fc_w, fc_b, w1, b1, w2, b2, w3, b3, (float*)d_out);
}

// round 2
// speedup vs baseline: 1.1807x; 1.1807x over previous
#include <cuda_runtime.h>

#define NNODE 17
#define TPB   272      // 17 nodes x 16 lanes-of-graphs
#define NG    32       // graphs per block (two sets of 16 per thread)

typedef unsigned long long u64;

// packed fp32x2 FMA (Blackwell); ptxas never auto-fuses this from C++
__device__ __forceinline__ u64 ffma2(u64 a, u64 b, u64 c) {
    u64 d;
    asm("fma.rn.f32x2 %0, %1, %2, %3;" : "=l"(d) : "l"(a), "l"(b), "l"(c));
    return d;
}
__device__ __forceinline__ u64 bcast2(float v) {
    u64 d; unsigned r = __float_as_uint(v);
    asm("mov.b64 %0, {%1, %1};" : "=l"(d) : "r"(r));
    return d;
}
__device__ __forceinline__ void unpk(u64 d, float& x, float& y) {
    unsigned a, b;
    asm("mov.b64 {%0, %1}, %2;" : "=r"(a), "=r"(b) : "l"(d));
    x = __uint_as_float(a); y = __uint_as_float(b);
}

// ---- dynamic shared layout (float offsets) ----
#define FCS   0        // fc_w: 32 rows x 160 (136 used, pad -> 640B rows, n-pair in one 128B line)
#define W1S   5120     // 8x16
#define B1S   5248     // 16
#define W2S   5264     // 16x32
#define B2S   5776     // 32
#define W3S   5808     // 32x32
#define B3S   6832     // 32
#define ZS    6864     // 32 graphs x 36 (32 used; pad kills bank conflicts)
#define ARENA 8016     // 544 rows x 36 floats (exchange + out staging)
#define SHFLOATS 27600 // 110400 bytes

extern __shared__ float sh[];

__global__ void __launch_bounds__(TPB, 1)
gnn_fused(const float* __restrict__ z,
          const float* __restrict__ fc_w, const float* __restrict__ fc_b,
          const float* __restrict__ w1,   const float* __restrict__ b1,
          const float* __restrict__ w2,   const float* __restrict__ b2,
          const float* __restrict__ w3,   const float* __restrict__ b3,
          float* __restrict__ out)
{
    const int tid = threadIdx.x;

    // ---------------- stage weights + z into shared ----------------
    for (int i = tid; i < 4352; i += TPB) {            // fc_w with row pad 136->160
        int k = i / 136, c = i - k * 136;
        sh[FCS + k * 160 + c] = fc_w[i];
    }
    for (int i = tid; i < 128;  i += TPB) sh[W1S + i] = w1[i];
    for (int i = tid; i < 512;  i += TPB) sh[W2S + i] = w2[i];
    for (int i = tid; i < 1024; i += TPB) sh[W3S + i] = w3[i];
    if (tid < 16)                         sh[B1S + tid] = b1[tid];
    else if (tid >= 32 && tid < 64)       sh[B2S + tid - 32] = b2[tid - 32];
    else if (tid >= 64 && tid < 96)       sh[B3S + tid - 64] = b3[tid - 64];
    {
        const float* zblk = z + (size_t)blockIdx.x * (NG * 32);
        for (int i = tid; i < NG * 32; i += TPB)
            sh[ZS + (i >> 5) * 36 + (i & 31)] = zblk[i];
    }
    __syncthreads();

    // thread = node n for graphs (g) and (g+16) of this block's 32 graphs
    const int n  = tid >> 4;
    const int g  = tid & 15;
    const int rp = (n == NNODE - 1) ? g         : tid + 16;  // row of node (n+1)%17
    const int rm = (n == 0)         ? 256 + g   : tid - 16;  // row of node (n-1)%17
    const float s3 = (1.0f / 3.0f);

    // ================= FC: x0 = z @ fc_w[:, 8n:8n+8] + fc_b =================
    float x0f[2][8];
    {
        u64 bias[4];
        const u64* fb = (const u64*)fc_b + n * 4;
        #pragma unroll
        for (int i = 0; i < 4; i++) bias[i] = __ldg(fb + i);
        #pragma unroll
        for (int s = 0; s < 2; s++) {
            float zr[32];
            const float4* zp = (const float4*)(sh + ZS + (g + 16 * s) * 36);
            #pragma unroll
            for (int i = 0; i < 8; i++) {
                float4 v = zp[i];
                zr[4*i] = v.x; zr[4*i+1] = v.y; zr[4*i+2] = v.z; zr[4*i+3] = v.w;
            }
            u64 acc[4] = {bias[0], bias[1], bias[2], bias[3]};
            #pragma unroll
            for (int k = 0; k < 32; k++) {
                u64 zz = bcast2(zr[k]);
                const ulonglong2* w = (const ulonglong2*)(sh + FCS + k * 160 + n * 8);
                ulonglong2 wa = w[0], wb = w[1];
                acc[0] = ffma2(zz, wa.x, acc[0]);
                acc[1] = ffma2(zz, wa.y, acc[1]);
                acc[2] = ffma2(zz, wb.x, acc[2]);
                acc[3] = ffma2(zz, wb.y, acc[3]);
            }
            #pragma unroll
            for (int i = 0; i < 4; i++) unpk(acc[i], x0f[s][2*i], x0f[s][2*i+1]);
        }
    }
    // ring exchange of x0
    #pragma unroll
    for (int s = 0; s < 2; s++) {
        float4* row = (float4*)(sh + ARENA + (s * 272 + tid) * 36);
        row[0] = make_float4(x0f[s][0], x0f[s][1], x0f[s][2], x0f[s][3]);
        row[1] = make_float4(x0f[s][4], x0f[s][5], x0f[s][6], x0f[s][7]);
    }
    __syncthreads();
    float a0[2][8];
    #pragma unroll
    for (int s = 0; s < 2; s++) {
        const float4* p = (const float4*)(sh + ARENA + (s * 272 + rp) * 36);
        const float4* m = (const float4*)(sh + ARENA + (s * 272 + rm) * 36);
        #pragma unroll
        for (int q = 0; q < 2; q++) {
            float4 pv = p[q], mv = m[q];
            a0[s][4*q+0] = (x0f[s][4*q+0] + pv.x + mv.x) * s3;
            a0[s][4*q+1] = (x0f[s][4*q+1] + pv.y + mv.y) * s3;
            a0[s][4*q+2] = (x0f[s][4*q+2] + pv.z + mv.z) * s3;
            a0[s][4*q+3] = (x0f[s][4*q+3] + pv.w + mv.w) * s3;
        }
    }
    __syncthreads();

    // ================= conv1: x1 = relu(a0 @ w1 + b1), 16 out =================
    float x1f[2][16];
    {
        u64 acc[2][8];
        const u64* bb = (const u64*)(sh + B1S);
        #pragma unroll
        for (int j = 0; j < 8; j++) { u64 b = bb[j]; acc[0][j] = b; acc[1][j] = b; }
        #pragma unroll
        for (int k = 0; k < 8; k++) {
            const ulonglong2* w = (const ulonglong2*)(sh + W1S + k * 16);
            u64 wv[8];
            #pragma unroll
            for (int q = 0; q < 4; q++) { ulonglong2 t = w[q]; wv[2*q] = t.x; wv[2*q+1] = t.y; }
            #pragma unroll
            for (int s = 0; s < 2; s++) {
                u64 av = bcast2(a0[s][k]);
                #pragma unroll
                for (int j = 0; j < 8; j++) acc[s][j] = ffma2(av, wv[j], acc[s][j]);
            }
        }
        #pragma unroll
        for (int s = 0; s < 2; s++)
            #pragma unroll
            for (int j = 0; j < 8; j++) {
                float x, y; unpk(acc[s][j], x, y);
                x1f[s][2*j]   = fmaxf(x, 0.0f);
                x1f[s][2*j+1] = fmaxf(y, 0.0f);
            }
    }
    #pragma unroll
    for (int s = 0; s < 2; s++) {
        float4* row = (float4*)(sh + ARENA + (s * 272 + tid) * 36);
        #pragma unroll
        for (int q = 0; q < 4; q++)
            row[q] = make_float4(x1f[s][4*q], x1f[s][4*q+1], x1f[s][4*q+2], x1f[s][4*q+3]);
    }
    __syncthreads();
    float a1[2][16];
    #pragma unroll
    for (int s = 0; s < 2; s++) {
        const float4* p = (const float4*)(sh + ARENA + (s * 272 + rp) * 36);
        const float4* m = (const float4*)(sh + ARENA + (s * 272 + rm) * 36);
        #pragma unroll
        for (int q = 0; q < 4; q++) {
            float4 pv = p[q], mv = m[q];
            a1[s][4*q+0] = (x1f[s][4*q+0] + pv.x + mv.x) * s3;
            a1[s][4*q+1] = (x1f[s][4*q+1] + pv.y + mv.y) * s3;
            a1[s][4*q+2] = (x1f[s][4*q+2] + pv.z + mv.z) * s3;
            a1[s][4*q+3] = (x1f[s][4*q+3] + pv.w + mv.w) * s3;
        }
    }
    __syncthreads();

    // ================= conv2: x2 = relu(a1 @ w2 + b2), 32 out =================
    float x2f[2][32];
    {
        u64 acc[2][16];
        const u64* bb = (const u64*)(sh + B2S);
        #pragma unroll
        for (int j = 0; j < 16; j++) { u64 b = bb[j]; acc[0][j] = b; acc[1][j] = b; }
        #pragma unroll
        for (int k = 0; k < 16; k++) {
            const ulonglong2* w = (const ulonglong2*)(sh + W2S + k * 32);
            u64 wv[16];
            #pragma unroll
            for (int q = 0; q < 8; q++) { ulonglong2 t = w[q]; wv[2*q] = t.x; wv[2*q+1] = t.y; }
            #pragma unroll
            for (int s = 0; s < 2; s++) {
                u64 av = bcast2(a1[s][k]);
                #pragma unroll
                for (int j = 0; j < 16; j++) acc[s][j] = ffma2(av, wv[j], acc[s][j]);
            }
        }
        #pragma unroll
        for (int s = 0; s < 2; s++)
            #pragma unroll
            for (int j = 0; j < 16; j++) {
                float x, y; unpk(acc[s][j], x, y);
                x2f[s][2*j]   = fmaxf(x, 0.0f);
                x2f[s][2*j+1] = fmaxf(y, 0.0f);
            }
    }
    #pragma unroll
    for (int s = 0; s < 2; s++) {
        float4* row = (float4*)(sh + ARENA + (s * 272 + tid) * 36);
        #pragma unroll
        for (int q = 0; q < 8; q++)
            row[q] = make_float4(x2f[s][4*q], x2f[s][4*q+1], x2f[s][4*q+2], x2f[s][4*q+3]);
    }
    __syncthreads();
    float a2[2][32];
    #pragma unroll
    for (int s = 0; s < 2; s++) {
        const float4* p = (const float4*)(sh + ARENA + (s * 272 + rp) * 36);
        const float4* m = (const float4*)(sh + ARENA + (s * 272 + rm) * 36);
        #pragma unroll
        for (int q = 0; q < 8; q++) {
            float4 pv = p[q], mv = m[q];
            a2[s][4*q+0] = (x2f[s][4*q+0] + pv.x + mv.x) * s3;
            a2[s][4*q+1] = (x2f[s][4*q+1] + pv.y + mv.y) * s3;
            a2[s][4*q+2] = (x2f[s][4*q+2] + pv.z + mv.z) * s3;
            a2[s][4*q+3] = (x2f[s][4*q+3] + pv.w + mv.w) * s3;
        }
    }
    __syncthreads();

    // ================= conv3: out = a2 @ w3 + b3, 32 out (no relu) ============
    {
        u64 acc[2][16];
        const u64* bb = (const u64*)(sh + B3S);
        #pragma unroll
        for (int j = 0; j < 16; j++) { u64 b = bb[j]; acc[0][j] = b; acc[1][j] = b; }
        #pragma unroll
        for (int k = 0; k < 32; k++) {
            const ulonglong2* w = (const ulonglong2*)(sh + W3S + k * 32);
            u64 wv[16];
            #pragma unroll
            for (int q = 0; q < 8; q++) { ulonglong2 t = w[q]; wv[2*q] = t.x; wv[2*q+1] = t.y; }
            #pragma unroll
            for (int s = 0; s < 2; s++) {
                u64 av = bcast2(a2[s][k]);
                #pragma unroll
                for (int j = 0; j < 16; j++) acc[s][j] = ffma2(av, wv[j], acc[s][j]);
            }
        }
        // stage results in out-layout rows: row = G*17 + n, G = g + 16s
        #pragma unroll
        for (int s = 0; s < 2; s++) {
            float of[32];
            #pragma unroll
            for (int j = 0; j < 16; j++) unpk(acc[s][j], of[2*j], of[2*j+1]);
            float4* row = (float4*)(sh + ARENA + ((g + 16 * s) * 17 + n) * 36);
            #pragma unroll
            for (int q = 0; q < 8; q++)
                row[q] = make_float4(of[4*q], of[4*q+1], of[4*q+2], of[4*q+3]);
        }
    }
    __syncthreads();

    // coalesced global write: 32*17*32 floats contiguous per block
    float4* og = (float4*)(out + (size_t)blockIdx.x * (NG * NNODE * 32));
    #pragma unroll
    for (int it = 0; it < 16; it++) {
        int q = tid + it * TPB;                 // 0 .. 4351
        int row = q >> 3, c = q & 7;
        og[q] = *(const float4*)(sh + ARENA + row * 36 + c * 4);
    }
}

extern "C" void kernel_launch(void* const* d_in, const int* in_sizes, int n_in,
                              void* d_out, int out_size) {
    const float* z    = (const float*)d_in[0];
    // d_in[1] = edge_index: fixed ring, degree==3 everywhere -> norm==1/3; unused
    const float* fc_w = (const float*)d_in[2];
    const float* fc_b = (const float*)d_in[3];
    const float* w1   = (const float*)d_in[4];
    const float* b1   = (const float*)d_in[5];
    const float* w2   = (const float*)d_in[6];
    const float* b2   = (const float*)d_in[7];
    const float* w3   = (const float*)d_in[8];
    const float* b3   = (const float*)d_in[9];

    cudaFuncSetAttribute(gnn_fused, cudaFuncAttributeMaxDynamicSharedMemorySize,
                         SHFLOATS * 4);

    const int B    = in_sizes[0] / 32;      // 65536 graphs
    const int grid = B / NG;                // 2048 blocks
    gnn_fused<<<grid, TPB, SHFLOATS * 4>>>(z, fc_w, fc_b, w1, b1, w2, b2, w3, b3,
                                           (float*)d_out);
}

// round 3
// speedup vs baseline: 1.2288x; 1.0408x over previous
#include <cuda_runtime.h>

#define NNODE 17
#define TPB   272      // 17 nodes x 16 graphs
#define NG    16       // graphs per block

typedef unsigned long long u64;

// packed fp32x2 FMA (Blackwell); ptxas never auto-fuses this from C++
__device__ __forceinline__ u64 ffma2(u64 a, u64 b, u64 c) {
    u64 d;
    asm("fma.rn.f32x2 %0, %1, %2, %3;" : "=l"(d) : "l"(a), "l"(b), "l"(c));
    return d;
}
__device__ __forceinline__ u64 bcast2(float v) {
    u64 d; unsigned r = __float_as_uint(v);
    asm("mov.b64 %0, {%1, %1};" : "=l"(d) : "r"(r));
    return d;
}
__device__ __forceinline__ void unpk(u64 d, float& x, float& y) {
    unsigned a, b;
    asm("mov.b64 {%0, %1}, %2;" : "=r"(a), "=r"(b) : "l"(d));
    x = __uint_as_float(a); y = __uint_as_float(b);
}

// ---- dynamic shared layout (float offsets) ----
#define FCS   0        // fc_w: 32 rows x 160 (136 used; n-pair of a warp sits in one 128B line)
#define W1S   5120     // 8x16
#define B1S   5248     // 16
#define W2S   5264     // 16x32
#define B2S   5776     // 32
#define W3S   5808     // 32x32
#define B3S   6832     // 32
#define ZS    6864     // 16 graphs x 36
#define ARENA 7440     // 272 rows x 36 floats (exchange + out staging)
#define SHFLOATS 17232 // 68928 bytes per block

extern __shared__ float sh[];

__global__ void __launch_bounds__(TPB, 2)
gnn_fused(const float* __restrict__ z,
          const float* __restrict__ fc_w, const float* __restrict__ fc_b,
          const float* __restrict__ w1,   const float* __restrict__ b1,
          const float* __restrict__ w2,   const float* __restrict__ b2,
          const float* __restrict__ w3,   const float* __restrict__ b3,
          float* __restrict__ out)
{
    const int tid = threadIdx.x;

    // ---------------- stage weights + z into shared ----------------
    for (int i = tid; i < 4352; i += TPB) {            // fc_w rows padded 136->160
        int k = i / 136, c = i - k * 136;
        sh[FCS + k * 160 + c] = fc_w[i];
    }
    for (int i = tid; i < 128;  i += TPB) sh[W1S + i] = w1[i];
    for (int i = tid; i < 512;  i += TPB) sh[W2S + i] = w2[i];
    for (int i = tid; i < 1024; i += TPB) sh[W3S + i] = w3[i];
    if (tid < 16)                         sh[B1S + tid] = b1[tid];
    else if (tid >= 32 && tid < 64)       sh[B2S + tid - 32] = b2[tid - 32];
    else if (tid >= 64 && tid < 96)       sh[B3S + tid - 64] = b3[tid - 64];
    {
        const float* zblk = z + (size_t)blockIdx.x * (NG * 32);
        for (int i = tid; i < NG * 32; i += TPB)
            sh[ZS + (i >> 5) * 36 + (i & 31)] = zblk[i];
    }
    __syncthreads();

    // thread = node n of graph g; warp holds 2 nodes x 16 graphs -> weight loads broadcast
    const int n  = tid >> 4;
    const int g  = tid & 15;
    const int rp = (n == NNODE - 1) ? g       : tid + 16;  // row of node (n+1)%17
    const int rm = (n == 0)         ? 256 + g : tid - 16;  // row of node (n-1)%17
    const float s3 = (1.0f / 3.0f);

    // ================= FC: x0 = z @ fc_w[:, 8n:8n+8] + fc_b =================
    float x0f[8];
    {
        u64 acc[4];
        const u64* fb = (const u64*)fc_b + n * 4;
        #pragma unroll
        for (int i = 0; i < 4; i++) acc[i] = __ldg(fb + i);
        float zr[32];
        const float4* zp = (const float4*)(sh + ZS + g * 36);
        #pragma unroll
        for (int i = 0; i < 8; i++) {
            float4 v = zp[i];
            zr[4*i] = v.x; zr[4*i+1] = v.y; zr[4*i+2] = v.z; zr[4*i+3] = v.w;
        }
        #pragma unroll
        for (int k = 0; k < 32; k++) {
            u64 zz = bcast2(zr[k]);
            const ulonglong2* w = (const ulonglong2*)(sh + FCS + k * 160 + n * 8);
            ulonglong2 wa = w[0], wb = w[1];
            acc[0] = ffma2(zz, wa.x, acc[0]);
            acc[1] = ffma2(zz, wa.y, acc[1]);
            acc[2] = ffma2(zz, wb.x, acc[2]);
            acc[3] = ffma2(zz, wb.y, acc[3]);
        }
        #pragma unroll
        for (int i = 0; i < 4; i++) unpk(acc[i], x0f[2*i], x0f[2*i+1]);
    }
    {
        float4* row = (float4*)(sh + ARENA + tid * 36);
        row[0] = make_float4(x0f[0], x0f[1], x0f[2], x0f[3]);
        row[1] = make_float4(x0f[4], x0f[5], x0f[6], x0f[7]);
    }
    __syncthreads();
    float a0[8];
    {
        const float4* p = (const float4*)(sh + ARENA + rp * 36);
        const float4* m = (const float4*)(sh + ARENA + rm * 36);
        #pragma unroll
        for (int q = 0; q < 2; q++) {
            float4 pv = p[q], mv = m[q];
            a0[4*q+0] = (x0f[4*q+0] + pv.x + mv.x) * s3;
            a0[4*q+1] = (x0f[4*q+1] + pv.y + mv.y) * s3;
            a0[4*q+2] = (x0f[4*q+2] + pv.z + mv.z) * s3;
            a0[4*q+3] = (x0f[4*q+3] + pv.w + mv.w) * s3;
        }
    }
    __syncthreads();

    // ================= conv1: x1 = relu(a0 @ w1 + b1), 16 out =================
    float x1f[16];
    {
        u64 acc[8];
        const u64* bb = (const u64*)(sh + B1S);
        #pragma unroll
        for (int j = 0; j < 8; j++) acc[j] = bb[j];
        #pragma unroll
        for (int k = 0; k < 8; k++) {
            u64 av = bcast2(a0[k]);
            const ulonglong2* w = (const ulonglong2*)(sh + W1S + k * 16);
            #pragma unroll
            for (int q = 0; q < 4; q++) {
                ulonglong2 t = w[q];
                acc[2*q]   = ffma2(av, t.x, acc[2*q]);
                acc[2*q+1] = ffma2(av, t.y, acc[2*q+1]);
            }
        }
        #pragma unroll
        for (int j = 0; j < 8; j++) {
            float x, y; unpk(acc[j], x, y);
            x1f[2*j]   = fmaxf(x, 0.0f);
            x1f[2*j+1] = fmaxf(y, 0.0f);
        }
    }
    {
        float4* row = (float4*)(sh + ARENA + tid * 36);
        #pragma unroll
        for (int q = 0; q < 4; q++)
            row[q] = make_float4(x1f[4*q], x1f[4*q+1], x1f[4*q+2], x1f[4*q+3]);
    }
    __syncthreads();
    float a1[16];
    {
        const float4* p = (const float4*)(sh + ARENA + rp * 36);
        const float4* m = (const float4*)(sh + ARENA + rm * 36);
        #pragma unroll
        for (int q = 0; q < 4; q++) {
            float4 pv = p[q], mv = m[q];
            a1[4*q+0] = (x1f[4*q+0] + pv.x + mv.x) * s3;
            a1[4*q+1] = (x1f[4*q+1] + pv.y + mv.y) * s3;
            a1[4*q+2] = (x1f[4*q+2] + pv.z + mv.z) * s3;
            a1[4*q+3] = (x1f[4*q+3] + pv.w + mv.w) * s3;
        }
    }
    __syncthreads();

    // ================= conv2: x2 = relu(a1 @ w2 + b2), 32 out =================
    float x2f[32];
    {
        u64 acc[16];
        const u64* bb = (const u64*)(sh + B2S);
        #pragma unroll
        for (int j = 0; j < 16; j++) acc[j] = bb[j];
        #pragma unroll
        for (int k = 0; k < 16; k++) {
            u64 av = bcast2(a1[k]);
            const ulonglong2* w = (const ulonglong2*)(sh + W2S + k * 32);
            #pragma unroll
            for (int q = 0; q < 8; q++) {
                ulonglong2 t = w[q];
                acc[2*q]   = ffma2(av, t.x, acc[2*q]);
                acc[2*q+1] = ffma2(av, t.y, acc[2*q+1]);
            }
        }
        #pragma unroll
        for (int j = 0; j < 16; j++) {
            float x, y; unpk(acc[j], x, y);
            x2f[2*j]   = fmaxf(x, 0.0f);
            x2f[2*j+1] = fmaxf(y, 0.0f);
        }
    }
    {
        float4* row = (float4*)(sh + ARENA + tid * 36);
        #pragma unroll
        for (int q = 0; q < 8; q++)
            row[q] = make_float4(x2f[4*q], x2f[4*q+1], x2f[4*q+2], x2f[4*q+3]);
    }
    __syncthreads();
    float a2[32];
    {
        const float4* p = (const float4*)(sh + ARENA + rp * 36);
        const float4* m = (const float4*)(sh + ARENA + rm * 36);
        #pragma unroll
        for (int q = 0; q < 8; q++) {
            float4 pv = p[q], mv = m[q];
            a2[4*q+0] = (x2f[4*q+0] + pv.x + mv.x) * s3;
            a2[4*q+1] = (x2f[4*q+1] + pv.y + mv.y) * s3;
            a2[4*q+2] = (x2f[4*q+2] + pv.z + mv.z) * s3;
            a2[4*q+3] = (x2f[4*q+3] + pv.w + mv.w) * s3;
        }
    }
    __syncthreads();

    // ================= conv3: out = a2 @ w3 + b3, 32 out (no relu) ============
    {
        u64 acc[16];
        const u64* bb = (const u64*)(sh + B3S);
        #pragma unroll
        for (int j = 0; j < 16; j++) acc[j] = bb[j];
        #pragma unroll
        for (int k = 0; k < 32; k++) {
            u64 av = bcast2(a2[k]);
            const ulonglong2* w = (const ulonglong2*)(sh + W3S + k * 32);
            #pragma unroll
            for (int q = 0; q < 8; q++) {
                ulonglong2 t = w[q];
                acc[2*q]   = ffma2(av, t.x, acc[2*q]);
                acc[2*q+1] = ffma2(av, t.y, acc[2*q+1]);
            }
        }
        float of[32];
        #pragma unroll
        for (int j = 0; j < 16; j++) unpk(acc[j], of[2*j], of[2*j+1]);
        // stage in out layout: row = g*17 + n
        float4* row = (float4*)(sh + ARENA + (g * 17 + n) * 36);
        #pragma unroll
        for (int q = 0; q < 8; q++)
            row[q] = make_float4(of[4*q], of[4*q+1], of[4*q+2], of[4*q+3]);
    }
    __syncthreads();

    // coalesced global write: 16*17*32 floats contiguous per block
    float4* og = (float4*)(out + (size_t)blockIdx.x * (NG * NNODE * 32));
    #pragma unroll
    for (int it = 0; it < 8; it++) {
        int q = tid + it * TPB;                 // 0 .. 2175
        int row = q >> 3, c = q & 7;
        og[q] = *(const float4*)(sh + ARENA + row * 36 + c * 4);
    }
}

extern "C" void kernel_launch(void* const* d_in, const int* in_sizes, int n_in,
                              void* d_out, int out_size) {
    const float* z    = (const float*)d_in[0];
    // d_in[1] = edge_index: fixed ring, degree==3 everywhere -> norm==1/3; unused
    const float* fc_w = (const float*)d_in[2];
    const float* fc_b = (const float*)d_in[3];
    const float* w1   = (const float*)d_in[4];
    const float* b1   = (const float*)d_in[5];
    const float* w2   = (const float*)d_in[6];
    const float* b2   = (const float*)d_in[7];
    const float* w3   = (const float*)d_in[8];
    const float* b3   = (const float*)d_in[9];

    cudaFuncSetAttribute(gnn_fused, cudaFuncAttributeMaxDynamicSharedMemorySize,
                         SHFLOATS * 4);

    const int B    = in_sizes[0] / 32;      // 65536 graphs
    const int grid = B / NG;                // 4096 blocks
    gnn_fused<<<grid, TPB, SHFLOATS * 4>>>(z, fc_w, fc_b, w1, b1, w2, b2, w3, b3,
                                           (float*)d_out);
}

// round 4
// speedup vs baseline: 1.2311x; 1.0018x over previous
#include <cuda_runtime.h>

#define NNODE 17
#define TPB   272      // 17 nodes x 16 graphs
#define NG    16       // graphs per block

typedef unsigned long long u64;

// packed fp32x2 FMA (Blackwell); ptxas never auto-fuses this from C++
__device__ __forceinline__ u64 ffma2(u64 a, u64 b, u64 c) {
    u64 d;
    asm("fma.rn.f32x2 %0, %1, %2, %3;" : "=l"(d) : "l"(a), "l"(b), "l"(c));
    return d;
}
__device__ __forceinline__ u64 bcast2(float v) {
    u64 d; unsigned r = __float_as_uint(v);
    asm("mov.b64 %0, {%1, %1};" : "=l"(d) : "r"(r));
    return d;
}
__device__ __forceinline__ void unpk(u64 d, float& x, float& y) {
    unsigned a, b;
    asm("mov.b64 {%0, %1}, %2;" : "=r"(a), "=r"(b) : "l"(d));
    x = __uint_as_float(a); y = __uint_as_float(b);
}

// ---- dynamic shared layout (float offsets) ----
#define FCS   0        // fc_w: 32 rows x 160 (136 used; n-pair of a warp sits in one 128B line)
#define W1S   5120     // 8x16
#define B1S   5248     // 16
#define W2S   5264     // 16x32
#define B2S   5776     // 32
#define W3S   5808     // 32x32
#define B3S   6832     // 32
#define ZS    6864     // 16 graphs x 36
#define ARENA 7440     // 272 rows x 36 floats (exchange + out staging)
#define SHFLOATS 17232 // 68928 bytes per block

extern __shared__ float sh[];

__global__ void __launch_bounds__(TPB, 2)
gnn_fused(const float* __restrict__ z,
          const float* __restrict__ fc_w, const float* __restrict__ fc_b,
          const float* __restrict__ w1,   const float* __restrict__ b1,
          const float* __restrict__ w2,   const float* __restrict__ b2,
          const float* __restrict__ w3,   const float* __restrict__ b3,
          float* __restrict__ out)
{
    const int tid = threadIdx.x;

    // ---------------- stage weights + z into shared ----------------
    for (int i = tid; i < 4352; i += TPB) {            // fc_w rows padded 136->160
        int k = i / 136, c = i - k * 136;
        sh[FCS + k * 160 + c] = fc_w[i];
    }
    for (int i = tid; i < 128;  i += TPB) sh[W1S + i] = w1[i];
    for (int i = tid; i < 512;  i += TPB) sh[W2S + i] = w2[i];
    for (int i = tid; i < 1024; i += TPB) sh[W3S + i] = w3[i];
    if (tid < 16)                         sh[B1S + tid] = b1[tid];
    else if (tid >= 32 && tid < 64)       sh[B2S + tid - 32] = b2[tid - 32];
    else if (tid >= 64 && tid < 96)       sh[B3S + tid - 64] = b3[tid - 64];
    {
        const float* zblk = z + (size_t)blockIdx.x * (NG * 32);
        for (int i = tid; i < NG * 32; i += TPB)
            sh[ZS + (i >> 5) * 36 + (i & 31)] = zblk[i];
    }
    __syncthreads();

    // thread = node n of graph g; warp holds 2 nodes x 16 graphs -> weight loads broadcast
    const int n  = tid >> 4;
    const int g  = tid & 15;
    const int rp = (n == NNODE - 1) ? g       : tid + 16;  // row of node (n+1)%17
    const int rm = (n == 0)         ? 256 + g : tid - 16;  // row of node (n-1)%17
    const float s3 = (1.0f / 3.0f);

    // ================= FC: x0 = z @ fc_w[:, 8n:8n+8] + fc_b =================
    float x0f[8];
    {
        u64 acc[4];
        const u64* fb = (const u64*)fc_b + n * 4;
        #pragma unroll
        for (int i = 0; i < 4; i++) acc[i] = __ldg(fb + i);
        float zr[32];
        const float4* zp = (const float4*)(sh + ZS + g * 36);
        #pragma unroll
        for (int i = 0; i < 8; i++) {
            float4 v = zp[i];
            zr[4*i] = v.x; zr[4*i+1] = v.y; zr[4*i+2] = v.z; zr[4*i+3] = v.w;
        }
        #pragma unroll
        for (int k = 0; k < 32; k++) {
            u64 zz = bcast2(zr[k]);
            const ulonglong2* w = (const ulonglong2*)(sh + FCS + k * 160 + n * 8);
            ulonglong2 wa = w[0], wb = w[1];
            acc[0] = ffma2(zz, wa.x, acc[0]);
            acc[1] = ffma2(zz, wa.y, acc[1]);
            acc[2] = ffma2(zz, wb.x, acc[2]);
            acc[3] = ffma2(zz, wb.y, acc[3]);
        }
        #pragma unroll
        for (int i = 0; i < 4; i++) unpk(acc[i], x0f[2*i], x0f[2*i+1]);
    }
    {
        float4* row = (float4*)(sh + ARENA + tid * 36);
        row[0] = make_float4(x0f[0], x0f[1], x0f[2], x0f[3]);
        row[1] = make_float4(x0f[4], x0f[5], x0f[6], x0f[7]);
    }
    __syncthreads();
    float a0[8];
    {
        const float4* p = (const float4*)(sh + ARENA + rp * 36);
        const float4* m = (const float4*)(sh + ARENA + rm * 36);
        #pragma unroll
        for (int q = 0; q < 2; q++) {
            float4 pv = p[q], mv = m[q];
            a0[4*q+0] = (x0f[4*q+0] + pv.x + mv.x) * s3;
            a0[4*q+1] = (x0f[4*q+1] + pv.y + mv.y) * s3;
            a0[4*q+2] = (x0f[4*q+2] + pv.z + mv.z) * s3;
            a0[4*q+3] = (x0f[4*q+3] + pv.w + mv.w) * s3;
        }
    }
    __syncthreads();

    // ================= conv1: x1 = relu(a0 @ w1 + b1), 16 out =================
    float x1f[16];
    {
        u64 acc[8];
        const u64* bb = (const u64*)(sh + B1S);
        #pragma unroll
        for (int j = 0; j < 8; j++) acc[j] = bb[j];
        #pragma unroll
        for (int k = 0; k < 8; k++) {
            u64 av = bcast2(a0[k]);
            const ulonglong2* w = (const ulonglong2*)(sh + W1S + k * 16);
            #pragma unroll
            for (int q = 0; q < 4; q++) {
                ulonglong2 t = w[q];
                acc[2*q]   = ffma2(av, t.x, acc[2*q]);
                acc[2*q+1] = ffma2(av, t.y, acc[2*q+1]);
            }
        }
        #pragma unroll
        for (int j = 0; j < 8; j++) {
            float x, y; unpk(acc[j], x, y);
            x1f[2*j]   = fmaxf(x, 0.0f);
            x1f[2*j+1] = fmaxf(y, 0.0f);
        }
    }
    {
        float4* row = (float4*)(sh + ARENA + tid * 36);
        #pragma unroll
        for (int q = 0; q < 4; q++)
            row[q] = make_float4(x1f[4*q], x1f[4*q+1], x1f[4*q+2], x1f[4*q+3]);
    }
    __syncthreads();
    float a1[16];
    {
        const float4* p = (const float4*)(sh + ARENA + rp * 36);
        const float4* m = (const float4*)(sh + ARENA + rm * 36);
        #pragma unroll
        for (int q = 0; q < 4; q++) {
            float4 pv = p[q], mv = m[q];
            a1[4*q+0] = (x1f[4*q+0] + pv.x + mv.x) * s3;
            a1[4*q+1] = (x1f[4*q+1] + pv.y + mv.y) * s3;
            a1[4*q+2] = (x1f[4*q+2] + pv.z + mv.z) * s3;
            a1[4*q+3] = (x1f[4*q+3] + pv.w + mv.w) * s3;
        }
    }
    __syncthreads();

    // ================= conv2: x2 = relu(a1 @ w2 + b2), 32 out =================
    float x2f[32];
    {
        u64 acc[16];
        const u64* bb = (const u64*)(sh + B2S);
        #pragma unroll
        for (int j = 0; j < 16; j++) acc[j] = bb[j];
        #pragma unroll
        for (int k = 0; k < 16; k++) {
            u64 av = bcast2(a1[k]);
            const ulonglong2* w = (const ulonglong2*)(sh + W2S + k * 32);
            #pragma unroll
            for (int q = 0; q < 8; q++) {
                ulonglong2 t = w[q];
                acc[2*q]   = ffma2(av, t.x, acc[2*q]);
                acc[2*q+1] = ffma2(av, t.y, acc[2*q+1]);
            }
        }
        #pragma unroll
        for (int j = 0; j < 16; j++) {
            float x, y; unpk(acc[j], x, y);
            x2f[2*j]   = fmaxf(x, 0.0f);
            x2f[2*j+1] = fmaxf(y, 0.0f);
        }
    }
    {
        float4* row = (float4*)(sh + ARENA + tid * 36);
        #pragma unroll
        for (int q = 0; q < 8; q++)
            row[q] = make_float4(x2f[4*q], x2f[4*q+1], x2f[4*q+2], x2f[4*q+3]);
    }
    __syncthreads();
    float a2[32];
    {
        const float4* p = (const float4*)(sh + ARENA + rp * 36);
        const float4* m = (const float4*)(sh + ARENA + rm * 36);
        #pragma unroll
        for (int q = 0; q < 8; q++) {
            float4 pv = p[q], mv = m[q];
            a2[4*q+0] = (x2f[4*q+0] + pv.x + mv.x) * s3;
            a2[4*q+1] = (x2f[4*q+1] + pv.y + mv.y) * s3;
            a2[4*q+2] = (x2f[4*q+2] + pv.z + mv.z) * s3;
            a2[4*q+3] = (x2f[4*q+3] + pv.w + mv.w) * s3;
        }
    }
    __syncthreads();

    // ================= conv3: out = a2 @ w3 + b3, 32 out (no relu) ============
    {
        u64 acc[16];
        const u64* bb = (const u64*)(sh + B3S);
        #pragma unroll
        for (int j = 0; j < 16; j++) acc[j] = bb[j];
        #pragma unroll
        for (int k = 0; k < 32; k++) {
            u64 av = bcast2(a2[k]);
            const ulonglong2* w = (const ulonglong2*)(sh + W3S + k * 32);
            #pragma unroll
            for (int q = 0; q < 8; q++) {
                ulonglong2 t = w[q];
                acc[2*q]   = ffma2(av, t.x, acc[2*q]);
                acc[2*q+1] = ffma2(av, t.y, acc[2*q+1]);
            }
        }
        float of[32];
        #pragma unroll
        for (int j = 0; j < 16; j++) unpk(acc[j], of[2*j], of[2*j+1]);
        // stage in out layout: row = g*17 + n
        float4* row = (float4*)(sh + ARENA + (g * 17 + n) * 36);
        #pragma unroll
        for (int q = 0; q < 8; q++)
            row[q] = make_float4(of[4*q], of[4*q+1], of[4*q+2], of[4*q+3]);
    }
    __syncthreads();

    // coalesced global write: 16*17*32 floats contiguous per block
    float4* og = (float4*)(out + (size_t)blockIdx.x * (NG * NNODE * 32));
    #pragma unroll
    for (int it = 0; it < 8; it++) {
        int q = tid + it * TPB;                 // 0 .. 2175
        int row = q >> 3, c = q & 7;
        og[q] = *(const float4*)(sh + ARENA + row * 36 + c * 4);
    }
}

extern "C" void kernel_launch(void* const* d_in, const int* in_sizes, int n_in,
                              void* d_out, int out_size) {
    const float* z    = (const float*)d_in[0];
    // d_in[1] = edge_index: fixed ring, degree==3 everywhere -> norm==1/3; unused
    const float* fc_w = (const float*)d_in[2];
    const float* fc_b = (const float*)d_in[3];
    const float* w1   = (const float*)d_in[4];
    const float* b1   = (const float*)d_in[5];
    const float* w2   = (const float*)d_in[6];
    const float* b2   = (const float*)d_in[7];
    const float* w3   = (const float*)d_in[8];
    const float* b3   = (const float*)d_in[9];

    cudaFuncSetAttribute(gnn_fused, cudaFuncAttributeMaxDynamicSharedMemorySize,
                         SHFLOATS * 4);

    const int B    = in_sizes[0] / 32;      // 65536 graphs
    const int grid = B / NG;                // 4096 blocks
    gnn_fused<<<grid, TPB, SHFLOATS * 4>>>(z, fc_w, fc_b, w1, b1, w2, b2, w3, b3,
                                           (float*)d_out);
}